// round 1
// baseline (speedup 1.0000x reference)
#include <cuda_runtime.h>
#include <cuda_bf16.h>

// Problem: 2-layer RNN (hidden=1), S=2048, B=256, I=128.
// out[b] = sigmoid(h2[S-1, b]) where
//   xp[s,b] = x[s,b,:] . W_ih0 + b_ih0 + b_hh0
//   h1 = tanh(xp + h1*W_hh0)
//   h2 = tanh(h1*W_ih1 + b_ih1 + b_hh1 + h2*W_hh1)

#define S_LEN 2048
#define B_SZ  256
#define I_SZ  128

// Scratch for the projected inputs, [s][b] layout (b contiguous).
__device__ float g_xp[S_LEN * B_SZ];

__device__ __forceinline__ float tanh_fast(float x) {
    float y;
    asm("tanh.approx.f32 %0, %1;" : "=f"(y) : "f"(x));
    return y;
}

// ---------------------------------------------------------------------------
// Phase 1: xp[s,b] = dot(x[s,b,:], w) + bias0.  One warp per (s,b) row.
// Each lane loads one float4 of x (coalesced 512B per warp) and one float4 of
// w (L1-resident), dot4, warp shfl reduction, lane 0 stores.
// ---------------------------------------------------------------------------
__global__ __launch_bounds__(256) void rnn_phase1(
    const float* __restrict__ x,
    const float* __restrict__ w_ih0,
    const float* __restrict__ b_ih0,
    const float* __restrict__ b_hh0)
{
    const int warp = (blockIdx.x * blockDim.x + threadIdx.x) >> 5; // row index
    const int lane = threadIdx.x & 31;

    const float4 xv = reinterpret_cast<const float4*>(x)[warp * 32 + lane];
    const float4 wv = reinterpret_cast<const float4*>(w_ih0)[lane];

    float s = xv.x * wv.x;
    s = fmaf(xv.y, wv.y, s);
    s = fmaf(xv.z, wv.z, s);
    s = fmaf(xv.w, wv.w, s);

    #pragma unroll
    for (int o = 16; o; o >>= 1)
        s += __shfl_xor_sync(0xffffffffu, s, o);

    if (lane == 0)
        g_xp[warp] = s + b_ih0[0] + b_hh0[0];
}

// ---------------------------------------------------------------------------
// Phase 2: the recurrence. One thread per batch element, 8 blocks x 32 threads
// so each warp owns its SMSP (MUFU.TANH rt=8/SMSP would interfere otherwise).
// xp loads are software-pipelined in chunks of 16 steps (>=320 cyc of slack
// against ~250 cyc L2 latency). The h2 recurrent cycle is arranged as
// fma+tanh = 20 cyc by keeping the h1 term off the cycle.
// ---------------------------------------------------------------------------
__global__ __launch_bounds__(32) void rnn_phase2(
    const float* __restrict__ w_hh0,
    const float* __restrict__ w_ih1,
    const float* __restrict__ w_hh1,
    const float* __restrict__ b_ih1,
    const float* __restrict__ b_hh1,
    float* __restrict__ out)
{
    const int b = blockIdx.x * 32 + threadIdx.x;   // 0..255

    const float w00 = w_hh0[0];
    const float a1  = w_ih1[0];
    const float d1  = w_hh1[0];
    const float c1  = b_ih1[0] + b_hh1[0];

    float h1 = 0.0f, h2 = 0.0f;

    float cur[16], nxt[16];

    const float* __restrict__ xp = g_xp;

    #pragma unroll
    for (int j = 0; j < 16; j++)
        cur[j] = xp[j * B_SZ + b];

    for (int base = 0; base < S_LEN; base += 16) {
        const int nb = base + 16;
        if (nb < S_LEN) {
            #pragma unroll
            for (int j = 0; j < 16; j++)
                nxt[j] = xp[(nb + j) * B_SZ + b];
        }
        #pragma unroll
        for (int j = 0; j < 16; j++) {
            // layer-0 recurrence: cycle = fma(4) + tanh(16) = 20 cyc
            h1 = tanh_fast(fmaf(h1, w00, cur[j]));
            // layer-1: keep h1 contribution off the h2 cycle:
            //   s = fma(h1_new, a1, c1)   (depends on h1, not h2)
            //   h2 = tanh(fma(h2, d1, s)) (cycle = fma + tanh = 20 cyc)
            float s = fmaf(h1, a1, c1);
            h2 = tanh_fast(fmaf(h2, d1, s));
        }
        #pragma unroll
        for (int j = 0; j < 16; j++)
            cur[j] = nxt[j];
    }

    // sigmoid, h2 in (-1,1) so __expf precision is ample
    out[b] = 1.0f / (1.0f + __expf(-h2));
}

// ---------------------------------------------------------------------------
extern "C" void kernel_launch(void* const* d_in, const int* in_sizes, int n_in,
                              void* d_out, int out_size)
{
    const float* x     = (const float*)d_in[0];
    const float* Wih0  = (const float*)d_in[1];
    const float* Whh0  = (const float*)d_in[2];
    const float* bih0  = (const float*)d_in[3];
    const float* bhh0  = (const float*)d_in[4];
    const float* Wih1  = (const float*)d_in[5];
    const float* Whh1  = (const float*)d_in[6];
    const float* bih1  = (const float*)d_in[7];
    const float* bhh1  = (const float*)d_in[8];
    float* out = (float*)d_out;

    // 524288 rows, 1 warp each, 8 warps per block -> 65536 blocks
    rnn_phase1<<<(S_LEN * B_SZ) / 8, 256>>>(x, Wih0, bih0, bhh0);
    rnn_phase2<<<8, 32>>>(Whh0, Wih1, Whh1, bih1, bhh1, out);
}